// round 15
// baseline (speedup 1.0000x reference)
#include <cuda_runtime.h>

#define NN 10000
#define EE 160000
#define GG 64
#define HH 32
#define WIDTH 64   // ELL width; degree ~ Binomial(160k, 1e-4), P(>=64) ~ 1e-20
#define NTILES 313 // ceil(NN/32)

// ---- scratch (device globals; referenced ONLY in device code) ----
// INVARIANT: d_deg and d_count are ZERO before every call (BSS zero on call 1;
// k_spmv2_out resets them after use on every call). deg semantics: sum of
// incoming w; the self-loop "+1" is applied as (1 + deg) at use sites.
__device__ float  d_deg[NN];
__device__ int    d_count[NN];
__device__ float2 d_ell[NN * WIDTH];    // {src bits, w}; spmv1 normalizes in place; pad slots stay {0,0}
__device__ float  d_xt[NN * GG];        // x transposed (N, G)
__device__ float  d_zt[NN * GG];        // layer-1 output transposed

// ---- K_A: fused edge pass (blocks 0..624) + x transpose (blocks 625..1250) ----
__global__ void k_build(const int* __restrict__ ei, const float* __restrict__ w,
                        const float* __restrict__ x) {
    int b = blockIdx.x;
    if (b < EE / 256) {
        int i = b * 256 + threadIdx.x;          // exact: 625*256 == EE
        int   s  = ei[i];
        int   d  = ei[EE + i];
        float ww = w[i];
        int p = atomicAdd(&d_count[d], 1);
        if (p < WIDTH) d_ell[d * WIDTH + p] = make_float2(__int_as_float(s), ww);
        atomicAdd(&d_deg[d], ww);               // no return use -> REDG
    } else {
        int t  = b - EE / 256;
        int n0 = (t % NTILES) * 32, g0 = (t / NTILES) * 32;
        __shared__ float tl[32][33];
        int tx = threadIdx.x & 31, ty = threadIdx.x >> 5;   // 32 x 8
        #pragma unroll
        for (int k = 0; k < 4; k++) {
            int g = g0 + ty + 8 * k, n = n0 + tx;
            if (n < NN) tl[ty + 8 * k][tx] = x[g * NN + n];
        }
        __syncthreads();
        #pragma unroll
        for (int k = 0; k < 4; k++) {
            int n = n0 + ty + 8 * k, g = g0 + tx;
            if (n < NN) d_xt[n * GG + g] = tl[tx][ty + 8 * k];
        }
    }
}

// ---- static 8-edge block: 8 shfl-broadcasts -> up to 8 PREDICATED gathers -> FMAs ----
__device__ __forceinline__ void chunk8(const float2* __restrict__ in2, int lane, int cnt,
                                       float2& acc, float ex, float ey, int lb) {
    int   s[8];
    float n[8];
    #pragma unroll
    for (int k = 0; k < 8; k++) {
        s[k] = __float_as_int(__shfl_sync(0xffffffffu, ex, lb + k));
        n[k] = __shfl_sync(0xffffffffu, ey, lb + k);
    }
    float2 v[8];
    #pragma unroll
    for (int k = 0; k < 8; k++) {
        v[k] = make_float2(0.f, 0.f);
        if (lb + k < cnt) v[k] = in2[s[k] * 32 + lane];   // @P LDG.64, uniform pred
    }
    #pragma unroll
    for (int k = 0; k < 8; k++) {
        acc.x = fmaf(n[k], v[k].x, acc.x);
        acc.y = fmaf(n[k], v[k].y, acc.y);
    }
}

// ---- SpMV layer 1: warp-per-row; normalizes ELL in registers (writes back for
//      layer 2), aggregates, applies fused relu-MLP, writes d_zt ----
__global__ void k_spmv1(const float* __restrict__ W1, const float* __restrict__ b1,
                        const float* __restrict__ W2) {
    __shared__ float sW1[HH], sB1[HH], sW2[HH];
    if (threadIdx.x < HH) {
        sW1[threadIdx.x] = W1[threadIdx.x];
        sB1[threadIdx.x] = b1[threadIdx.x];
        sW2[threadIdx.x] = W2[threadIdx.x];
    }
    __syncthreads();

    int row  = (blockIdx.x * blockDim.x + threadIdx.x) >> 5;   // grid = exactly NN warps
    int lane = threadIdx.x & 31;
    const float2* in2 = (const float2*)d_xt;

    float2* ell2 = d_ell + row * WIDTH;
    int cnt = min(d_count[row], WIDTH);

    float2 elo = ell2[lane];
    float dr = rsqrtf(1.0f + d_deg[row]);
    float sn = dr * dr;

    // normalize staged entries in registers; pad slots: 0 * anything = 0
    elo.y *= rsqrtf(1.0f + d_deg[__float_as_int(elo.x)]) * dr;
    ell2[lane] = elo;                              // write back for layer 2

    float2 xs = in2[row * 32 + lane];
    float2 acc = make_float2(sn * xs.x, sn * xs.y);

    chunk8(in2, lane, cnt, acc, elo.x, elo.y, 0);
    chunk8(in2, lane, cnt, acc, elo.x, elo.y, 8);
    chunk8(in2, lane, cnt, acc, elo.x, elo.y, 16);
    chunk8(in2, lane, cnt, acc, elo.x, elo.y, 24);

    if (cnt > 32) {                                // rare tail (P ~ 1e-4)
        float2 ehi = ell2[32 + lane];
        ehi.y *= rsqrtf(1.0f + d_deg[__float_as_int(ehi.x)]) * dr;
        ell2[32 + lane] = ehi;
        int ch = cnt - 32;
        chunk8(in2, lane, ch, acc, ehi.x, ehi.y, 0);
        chunk8(in2, lane, ch, acc, ehi.x, ehi.y, 8);
        chunk8(in2, lane, ch, acc, ehi.x, ehi.y, 16);
        chunk8(in2, lane, ch, acc, ehi.x, ehi.y, 24);
    }

    float z0 = 0.f, z1 = 0.f;
    #pragma unroll
    for (int j = 0; j < HH; j++) {
        z0 += fmaxf(fmaf(acc.x, sW1[j], sB1[j]), 0.f) * sW2[j];
        z1 += fmaxf(fmaf(acc.y, sW1[j], sB1[j]), 0.f) * sW2[j];
    }
    ((float2*)d_zt)[row * 32 + lane] = make_float2(z0, z1);
}

// ---- SpMV layer 2 + fused transpose/mask-merge output + state reset ----
// 8 rows per block. Results staged in a smem tile, then written straight to the
// (G,N)-layout output with the mask merge (float2/int2: 8B aligned since NN even
// and n0 multiple of 8). Resets d_deg/d_count for the next replay after use.
__global__ void k_spmv2_out(const float* __restrict__ x, const int* __restrict__ mask,
                            float* __restrict__ out, const float* __restrict__ b2) {
    __shared__ float sT[GG][9];
    int tid = threadIdx.x, wid = tid >> 5, lane = tid & 31;
    int row = blockIdx.x * 8 + wid;
    const float2* in2 = (const float2*)d_zt;

    float2* ell2 = d_ell + row * WIDTH;
    int cnt = min(d_count[row], WIDTH);
    float2 elo = ell2[lane];                       // already normalized by spmv1
    float sn = 1.0f / (1.0f + d_deg[row]);
    if (lane == 0) { d_deg[row] = 0.f; d_count[row] = 0; }   // reset for next call

    float2 xs = in2[row * 32 + lane];
    float2 acc = make_float2(sn * xs.x, sn * xs.y);

    chunk8(in2, lane, cnt, acc, elo.x, elo.y, 0);
    chunk8(in2, lane, cnt, acc, elo.x, elo.y, 8);
    chunk8(in2, lane, cnt, acc, elo.x, elo.y, 16);
    chunk8(in2, lane, cnt, acc, elo.x, elo.y, 24);
    if (cnt > 32) {
        float2 ehi = ell2[32 + lane];
        int ch = cnt - 32;
        chunk8(in2, lane, ch, acc, ehi.x, ehi.y, 0);
        chunk8(in2, lane, ch, acc, ehi.x, ehi.y, 8);
        chunk8(in2, lane, ch, acc, ehi.x, ehi.y, 16);
        chunk8(in2, lane, ch, acc, ehi.x, ehi.y, 24);
    }

    float bb = __ldg(b2);
    sT[2 * lane][wid]     = acc.x + bb;            // g = 2*lane
    sT[2 * lane + 1][wid] = acc.y + bb;            // g = 2*lane + 1
    __syncthreads();

    // output: thread -> (g, pair of n); 8 consecutive floats per g-segment
    int g = tid >> 2, j = tid & 3;
    int n = blockIdx.x * 8 + 2 * j;
    int idx = g * NN + n;                          // 8B aligned
    float f0 = sT[g][2 * j], f1 = sT[g][2 * j + 1];
    int2   m2 = *(const int2*)(mask + idx);
    float2 xx = *(const float2*)(x + idx);
    float2 o;
    o.x = m2.x ? xx.x : f0;
    o.y = m2.y ? xx.y : f1;
    *(float2*)(out + idx) = o;
}

extern "C" void kernel_launch(void* const* d_in, const int* in_sizes, int n_in,
                              void* d_out, int out_size) {
    const float* x    = (const float*)d_in[0];
    const int*   mask = (const int*)d_in[1];      // jax bool -> int32 on the wire
    const int*   ei   = (const int*)d_in[2];
    const float* w    = (const float*)d_in[3];
    const float* W1   = (const float*)d_in[4];
    const float* b1   = (const float*)d_in[5];
    const float* W2   = (const float*)d_in[6];
    const float* b2   = (const float*)d_in[7];
    float*       out  = (float*)d_out;

    k_build<<<EE / 256 + 2 * NTILES, 256>>>(ei, w, x);  // edges + x-transpose
    k_spmv1<<<NN / 8, 256>>>(W1, b1, W2);               // warp-per-row; normalizes ELL
    k_spmv2_out<<<NN / 8, 256>>>(x, mask, out, b2);     // spmv2 + transpose + merge + reset
}

// round 16
// speedup vs baseline: 1.0744x; 1.0744x over previous
#include <cuda_runtime.h>

#define NN 10000
#define EE 160000
#define GG 64
#define HH 32
#define WIDTH 64   // ELL width; degree ~ Binomial(160k, 1e-4), P(>=64) ~ 1e-20

// ---- scratch (device globals; referenced ONLY in device code) ----
// INVARIANT: d_deg/d_count are ZERO before every call (BSS zero on call 1;
// k_out resets them each call). deg = sum of incoming w; self-loop "+1" is
// applied as (1 + deg) where dinv is computed. ELL stays RAW (never normalized).
__device__ float  d_deg[NN];
__device__ int    d_count[NN];
__device__ float  d_dinv[NN];           // rsqrt(1 + deg), written by k_scale
__device__ float2 d_ell[NN * WIDTH];    // {src bits, raw w}; pad slots {0,0}
__device__ float  d_xt[NN * GG];        // xhat = dinv * x, transposed (N, G)
__device__ float  d_zt[NN * GG];        // z' = dinv * z, transposed (N, G)
__device__ float  d_ot[NN * GG];        // layer-2 output transposed

// ---- K1: edge pass: raw ELL build + degree accumulate (1 edge/thread) ----
__global__ void k_build(const int* __restrict__ ei, const float* __restrict__ w) {
    int i = blockIdx.x * blockDim.x + threadIdx.x;
    if (i < EE) {
        int   s  = ei[i];
        int   d  = ei[EE + i];
        float ww = w[i];
        int p = atomicAdd(&d_count[d], 1);
        if (p < WIDTH) d_ell[d * WIDTH + p] = make_float2(__int_as_float(s), ww);
        atomicAdd(&d_deg[d], ww);      // no return use -> REDG
    }
}

// ---- K2: transpose x (G,N)->(N,G) scaled by dinv[n]; also stores d_dinv ----
__global__ void k_scale(const float* __restrict__ x) {
    __shared__ float t[32][33];
    int n0 = blockIdx.x * 32, g0 = blockIdx.y * 32;
    int tx = threadIdx.x, ty = threadIdx.y;
    int n = n0 + tx, g = g0 + ty;
    if (n < NN) t[ty][tx] = x[g * NN + n];
    __syncthreads();
    n = n0 + ty; g = g0 + tx;
    if (n < NN) {
        float dv = rsqrtf(1.0f + d_deg[n]);
        if (tx == 0 && g0 == 0) d_dinv[n] = dv;
        d_xt[n * GG + g] = dv * t[tx][ty];
    }
}

// ---- static 8-edge block: 8 shfl-broadcasts -> up to 8 PREDICATED gathers -> FMAs ----
__device__ __forceinline__ void chunk8(const float2* __restrict__ in2, int lane, int cnt,
                                       float2& acc, float ex, float ey, int lb) {
    int   s[8];
    float n[8];
    #pragma unroll
    for (int k = 0; k < 8; k++) {
        s[k] = __float_as_int(__shfl_sync(0xffffffffu, ex, lb + k));
        n[k] = __shfl_sync(0xffffffffu, ey, lb + k);
    }
    float2 v[8];
    #pragma unroll
    for (int k = 0; k < 8; k++) {
        v[k] = make_float2(0.f, 0.f);
        if (lb + k < cnt) v[k] = in2[s[k] * 32 + lane];   // @P LDG.64, uniform pred
    }
    #pragma unroll
    for (int k = 0; k < 8; k++) {
        acc.x = fmaf(n[k], v[k].x, acc.x);
        acc.y = fmaf(n[k], v[k].y, acc.y);
    }
}

// ---- SpMV core on pre-scaled vectors with RAW weights ----
// result_before_epilogue = dinv[row] * (sum_e w_e * in[s_e] + in[row])
template <int LAYER>
__global__ void k_spmv(const float* __restrict__ W1, const float* __restrict__ b1,
                       const float* __restrict__ W2, const float* __restrict__ b2) {
    __shared__ float sW1[HH], sB1[HH], sW2[HH];
    if (LAYER == 1) {
        if (threadIdx.x < HH) {
            sW1[threadIdx.x] = W1[threadIdx.x];
            sB1[threadIdx.x] = b1[threadIdx.x];
            sW2[threadIdx.x] = W2[threadIdx.x];
        }
        __syncthreads();
    }

    int row  = (blockIdx.x * blockDim.x + threadIdx.x) >> 5;   // grid = exactly NN warps
    int lane = threadIdx.x & 31;
    const float2* in2 = (const float2*)(LAYER == 1 ? d_xt : d_zt);
    float2*       ou2 = (float2*)      (LAYER == 1 ? d_zt : d_ot);

    const float2* ell2 = d_ell + row * WIDTH;
    int cnt = min(d_count[row], WIDTH);
    float2 elo = ell2[lane];                       // raw {src, w}, coalesced 256B
    float dr = d_dinv[row];

    float2 xs = in2[row * 32 + lane];              // in[row] (already dinv-scaled)
    float2 acc = xs;                               // self-loop term (pre-scale)

    chunk8(in2, lane, cnt, acc, elo.x, elo.y, 0);
    chunk8(in2, lane, cnt, acc, elo.x, elo.y, 8);
    chunk8(in2, lane, cnt, acc, elo.x, elo.y, 16);
    chunk8(in2, lane, cnt, acc, elo.x, elo.y, 24);

    if (cnt > 32) {                                // rare tail (P ~ 1e-4)
        float2 ehi = ell2[32 + lane];
        int ch = cnt - 32;
        chunk8(in2, lane, ch, acc, ehi.x, ehi.y, 0);
        chunk8(in2, lane, ch, acc, ehi.x, ehi.y, 8);
        chunk8(in2, lane, ch, acc, ehi.x, ehi.y, 16);
        chunk8(in2, lane, ch, acc, ehi.x, ehi.y, 24);
    }

    acc.x *= dr;  acc.y *= dr;                     // y = dinv * (acc_raw + in[row])

    float2 res;
    if (LAYER == 1) {
        float z0 = 0.f, z1 = 0.f;
        #pragma unroll
        for (int j = 0; j < HH; j++) {
            z0 += fmaxf(fmaf(acc.x, sW1[j], sB1[j]), 0.f) * sW2[j];
            z1 += fmaxf(fmaf(acc.y, sW1[j], sB1[j]), 0.f) * sW2[j];
        }
        res = make_float2(dr * z0, dr * z1);       // store z' = dinv * z for layer 2
    } else {
        float bb = __ldg(b2);
        res = make_float2(acc.x + bb, acc.y + bb);
    }
    ou2[row * 32 + lane] = res;
}

// ---- K5: transpose out (N,G)->(G,N) + mask merge + state reset ----
__global__ void k_out(const float* __restrict__ x, const int* __restrict__ mask,
                      float* __restrict__ out) {
    __shared__ float t[32][33];
    int n0 = blockIdx.x * 32, g0 = blockIdx.y * 32;
    int tx = threadIdx.x, ty = threadIdx.y;
    int n = n0 + ty, g = g0 + tx;
    if (n < NN) t[ty][tx] = d_ot[n * GG + g];
    // reset per-call state for the next replay (one block column covers each n once)
    if (g0 == 0 && ty == 0) {
        int nr = n0 + tx;
        if (nr < NN) { d_deg[nr] = 0.f; d_count[nr] = 0; }
    }
    __syncthreads();
    n = n0 + tx; g = g0 + ty;
    if (n < NN) {
        int idx = g * NN + n;
        out[idx] = mask[idx] ? x[idx] : t[tx][ty];
    }
}

extern "C" void kernel_launch(void* const* d_in, const int* in_sizes, int n_in,
                              void* d_out, int out_size) {
    const float* x    = (const float*)d_in[0];
    const int*   mask = (const int*)d_in[1];      // jax bool -> int32 on the wire
    const int*   ei   = (const int*)d_in[2];
    const float* w    = (const float*)d_in[3];
    const float* W1   = (const float*)d_in[4];
    const float* b1   = (const float*)d_in[5];
    const float* W2   = (const float*)d_in[6];
    const float* b2   = (const float*)d_in[7];
    float*       out  = (float*)d_out;

    dim3 tb(32, 32);
    dim3 tg((NN + 31) / 32, GG / 32);
    k_build<<<(EE + 255) / 256, 256>>>(ei, w);
    k_scale<<<tg, tb>>>(x);                        // after build: reads deg
    k_spmv<1><<<NN / 8, 256>>>(W1, b1, W2, b2);
    k_spmv<2><<<NN / 8, 256>>>(W1, b1, W2, b2);
    k_out<<<tg, tb>>>(x, mask, out);
}

// round 17
// speedup vs baseline: 1.1289x; 1.0508x over previous
#include <cuda_runtime.h>

#define NN 10000
#define EE 160000
#define GG 64
#define HH 32
#define WIDTH 64   // ELL width; degree ~ Binomial(160k, 1e-4), P(>=64) ~ 1e-20

// ---- scratch (device globals; referenced ONLY in device code) ----
// INVARIANT: d_deg/d_count are ZERO before every call (BSS zero on call 1;
// k_out resets them each call). deg = sum of incoming w; self-loop "+1" is
// applied as (1 + deg) where dinv is computed. ELL stores RAW w and the
// PRE-SCALED source byte offset (src * 256 = src row stride in d_xt/d_zt).
__device__ float  d_deg[NN];
__device__ int    d_count[NN];
__device__ float  d_dinv[NN];           // rsqrt(1 + deg), written by k_scale
__device__ float2 d_ell[NN * WIDTH];    // {byte-offset bits, raw w}; pad slots {0,0}
__device__ float  d_xt[NN * GG];        // xhat = dinv * x, transposed (N, G)
__device__ float  d_zt[NN * GG];        // z' = dinv * z, transposed (N, G)
__device__ float  d_ot[NN * GG];        // layer-2 output transposed

// ---- K1: edge pass: raw ELL build + degree accumulate (1 edge/thread) ----
__global__ void k_build(const int* __restrict__ ei, const float* __restrict__ w) {
    int i = blockIdx.x * blockDim.x + threadIdx.x;
    if (i < EE) {
        int   s  = ei[i];
        int   d  = ei[EE + i];
        float ww = w[i];
        int p = atomicAdd(&d_count[d], 1);
        if (p < WIDTH) d_ell[d * WIDTH + p] = make_float2(__int_as_float(s << 8), ww);
        atomicAdd(&d_deg[d], ww);      // no return use -> REDG
    }
}

// ---- K2: transpose x (G,N)->(N,G) scaled by dinv[n]; also stores d_dinv ----
__global__ void k_scale(const float* __restrict__ x) {
    __shared__ float t[32][33];
    int n0 = blockIdx.x * 32, g0 = blockIdx.y * 32;
    int tx = threadIdx.x, ty = threadIdx.y;
    int n = n0 + tx, g = g0 + ty;
    if (n < NN) t[ty][tx] = x[g * NN + n];
    __syncthreads();
    n = n0 + ty; g = g0 + tx;
    if (n < NN) {
        float dv = rsqrtf(1.0f + d_deg[n]);
        if (tx == 0 && g0 == 0) d_dinv[n] = dv;
        d_xt[n * GG + g] = dv * t[tx][ty];
    }
}

// ---- static 8-edge block: 4 uniform LDS.128 (metadata broadcast) ->
//      up to 8 PREDICATED gathers (byte-offset addressing) -> FMAs ----
__device__ __forceinline__ void chunk8(const char* __restrict__ inb, int laneoff, int cnt,
                                       float2& acc, const float4* __restrict__ smeta, int lb) {
    // 4 uniform LDS.128: all lanes read the same address -> broadcast, no conflicts
    float4 m0 = smeta[(lb >> 1) + 0];   // edges lb+0, lb+1
    float4 m1 = smeta[(lb >> 1) + 1];   // edges lb+2, lb+3
    float4 m2 = smeta[(lb >> 1) + 2];   // edges lb+4, lb+5
    float4 m3 = smeta[(lb >> 1) + 3];   // edges lb+6, lb+7
    float2 v[8];
    #pragma unroll
    for (int k = 0; k < 8; k++) v[k] = make_float2(0.f, 0.f);
    if (lb + 0 < cnt) v[0] = *(const float2*)(inb + __float_as_int(m0.x) + laneoff);
    if (lb + 1 < cnt) v[1] = *(const float2*)(inb + __float_as_int(m0.z) + laneoff);
    if (lb + 2 < cnt) v[2] = *(const float2*)(inb + __float_as_int(m1.x) + laneoff);
    if (lb + 3 < cnt) v[3] = *(const float2*)(inb + __float_as_int(m1.z) + laneoff);
    if (lb + 4 < cnt) v[4] = *(const float2*)(inb + __float_as_int(m2.x) + laneoff);
    if (lb + 5 < cnt) v[5] = *(const float2*)(inb + __float_as_int(m2.z) + laneoff);
    if (lb + 6 < cnt) v[6] = *(const float2*)(inb + __float_as_int(m3.x) + laneoff);
    if (lb + 7 < cnt) v[7] = *(const float2*)(inb + __float_as_int(m3.z) + laneoff);
    acc.x = fmaf(m0.y, v[0].x, acc.x);  acc.y = fmaf(m0.y, v[0].y, acc.y);
    acc.x = fmaf(m0.w, v[1].x, acc.x);  acc.y = fmaf(m0.w, v[1].y, acc.y);
    acc.x = fmaf(m1.y, v[2].x, acc.x);  acc.y = fmaf(m1.y, v[2].y, acc.y);
    acc.x = fmaf(m1.w, v[3].x, acc.x);  acc.y = fmaf(m1.w, v[3].y, acc.y);
    acc.x = fmaf(m2.y, v[4].x, acc.x);  acc.y = fmaf(m2.y, v[4].y, acc.y);
    acc.x = fmaf(m2.w, v[5].x, acc.x);  acc.y = fmaf(m2.w, v[5].y, acc.y);
    acc.x = fmaf(m3.y, v[6].x, acc.x);  acc.y = fmaf(m3.y, v[6].y, acc.y);
    acc.x = fmaf(m3.w, v[7].x, acc.x);  acc.y = fmaf(m3.w, v[7].y, acc.y);
}

// ---- SpMV core: warp-per-row; ELL metadata parked in smem, broadcast via LDS ----
// result_before_epilogue = dinv[row] * (sum_e w_e * in[s_e] + in[row])
template <int LAYER>
__global__ void k_spmv(const float* __restrict__ W1, const float* __restrict__ b1,
                       const float* __restrict__ W2, const float* __restrict__ b2) {
    __shared__ float sW1[HH], sB1[HH], sW2[HH];
    __shared__ float2 smeta[8][WIDTH];             // 8 warps x 64 slots x 8B = 4KB
    if (LAYER == 1) {
        if (threadIdx.x < HH) {
            sW1[threadIdx.x] = W1[threadIdx.x];
            sB1[threadIdx.x] = b1[threadIdx.x];
            sW2[threadIdx.x] = W2[threadIdx.x];
        }
        __syncthreads();
    }

    int warp = threadIdx.x >> 5;
    int row  = (blockIdx.x * blockDim.x + threadIdx.x) >> 5;   // grid = exactly NN warps
    int lane = threadIdx.x & 31;
    int laneoff = lane * 8;                        // byte offset of this lane's float2
    const char* inb = (const char*)(LAYER == 1 ? d_xt : d_zt);
    float2*     ou2 = (float2*)    (LAYER == 1 ? d_zt : d_ot);

    const float2* ell2 = d_ell + row * WIDTH;
    int cnt = min(d_count[row], WIDTH);

    smeta[warp][lane] = ell2[lane];                // park slots 0..31 (coalesced LDG + STS)
    if (cnt > 32) smeta[warp][32 + lane] = ell2[32 + lane];  // rare hi half
    __syncwarp();

    float dr = d_dinv[row];
    const float4* sm = (const float4*)smeta[warp];

    float2 xs = *(const float2*)(inb + (row << 8) + laneoff);  // in[row] (dinv-scaled)
    float2 acc = xs;                               // self-loop term (pre-scale)

    chunk8(inb, laneoff, cnt, acc, sm, 0);
    chunk8(inb, laneoff, cnt, acc, sm, 8);
    chunk8(inb, laneoff, cnt, acc, sm, 16);
    chunk8(inb, laneoff, cnt, acc, sm, 24);
    if (cnt > 32) {                                // rare tail (P ~ 1e-4)
        chunk8(inb, laneoff, cnt, acc, sm, 32);
        chunk8(inb, laneoff, cnt, acc, sm, 40);
        chunk8(inb, laneoff, cnt, acc, sm, 48);
        chunk8(inb, laneoff, cnt, acc, sm, 56);
    }

    acc.x *= dr;  acc.y *= dr;                     // y = dinv * (acc_raw + in[row])

    float2 res;
    if (LAYER == 1) {
        float z0 = 0.f, z1 = 0.f;
        #pragma unroll
        for (int j = 0; j < HH; j++) {
            z0 += fmaxf(fmaf(acc.x, sW1[j], sB1[j]), 0.f) * sW2[j];
            z1 += fmaxf(fmaf(acc.y, sW1[j], sB1[j]), 0.f) * sW2[j];
        }
        res = make_float2(dr * z0, dr * z1);       // store z' = dinv * z for layer 2
    } else {
        float bb = __ldg(b2);
        res = make_float2(acc.x + bb, acc.y + bb);
    }
    ou2[row * 32 + lane] = res;
}

// ---- K5: transpose out (N,G)->(G,N) + mask merge + state reset ----
__global__ void k_out(const float* __restrict__ x, const int* __restrict__ mask,
                      float* __restrict__ out) {
    __shared__ float t[32][33];
    int n0 = blockIdx.x * 32, g0 = blockIdx.y * 32;
    int tx = threadIdx.x, ty = threadIdx.y;
    int n = n0 + ty, g = g0 + tx;
    if (n < NN) t[ty][tx] = d_ot[n * GG + g];
    // reset per-call state for the next replay (one block column covers each n once)
    if (g0 == 0 && ty == 0) {
        int nr = n0 + tx;
        if (nr < NN) { d_deg[nr] = 0.f; d_count[nr] = 0; }
    }
    __syncthreads();
    n = n0 + tx; g = g0 + ty;
    if (n < NN) {
        int idx = g * NN + n;
        out[idx] = mask[idx] ? x[idx] : t[tx][ty];
    }
}

extern "C" void kernel_launch(void* const* d_in, const int* in_sizes, int n_in,
                              void* d_out, int out_size) {
    const float* x    = (const float*)d_in[0];
    const int*   mask = (const int*)d_in[1];      // jax bool -> int32 on the wire
    const int*   ei   = (const int*)d_in[2];
    const float* w    = (const float*)d_in[3];
    const float* W1   = (const float*)d_in[4];
    const float* b1   = (const float*)d_in[5];
    const float* W2   = (const float*)d_in[6];
    const float* b2   = (const float*)d_in[7];
    float*       out  = (float*)d_out;

    dim3 tb(32, 32);
    dim3 tg((NN + 31) / 32, GG / 32);
    k_build<<<(EE + 255) / 256, 256>>>(ei, w);
    k_scale<<<tg, tb>>>(x);                        // after build: reads deg
    k_spmv<1><<<NN / 8, 256>>>(W1, b1, W2, b2);
    k_spmv<2><<<NN / 8, 256>>>(W1, b1, W2, b2);
    k_out<<<tg, tb>>>(x, mask, out);
}